// round 6
// baseline (speedup 1.0000x reference)
#include <cuda_runtime.h>
#include <cuda_fp16.h>
#include <cstdint>

// Problem constants
#define Bc   4
#define Tc   2048
#define Dc   1024
#define Hc   16
#define HDc  64
#define Mc   (Bc * Tc)          // 8192 rows
#define SCALING 0.125f

// Scratch (allocation-free rule)
__device__ __half g_q[Mc * Dc];        // [B,H,T,Hd]
__device__ __half g_k[Mc * Dc];        // [B,H,T,Hd]
__device__ __half g_v[Mc * Dc];        // [B,H,T,Hd]
__device__ __half g_attn[Mc * Dc];     // [B*T, D]
__device__ __half g_hs16[Mc * Dc];     // hidden_states fp16
__device__ __half g_wt16[4][Dc * Dc];  // W^T fp16, [N][K]
__device__ __half g_msk16[(size_t)Bc * Tc * Tc];  // mask fp16

// ---------------------------------------------------------------------------
// Helpers
// ---------------------------------------------------------------------------
__device__ __forceinline__ uint32_t smem_u32(const void* p) {
    uint32_t a;
    asm("{ .reg .u64 t; cvta.to.shared.u64 t, %1; cvt.u32.u64 %0, t; }"
        : "=r"(a) : "l"(p));
    return a;
}
__device__ __forceinline__ void cp16(uint32_t dst, const void* src) {
    asm volatile("cp.async.cg.shared.global [%0], [%1], 16;"
                 :: "r"(dst), "l"(src) : "memory");
}
#define CP_COMMIT() asm volatile("cp.async.commit_group;" ::: "memory")
#define CP_WAIT1()  asm volatile("cp.async.wait_group 1;" ::: "memory")
#define CP_WAIT0()  asm volatile("cp.async.wait_group 0;" ::: "memory")

// mma.sync m16n8k16 fp16 inputs, fp32 accumulate
__device__ __forceinline__ void mma16(float* d, const uint32_t* a, const uint32_t* b) {
    asm volatile(
        "mma.sync.aligned.m16n8k16.row.col.f32.f16.f16.f32 "
        "{%0,%1,%2,%3}, {%4,%5,%6,%7}, {%8,%9}, {%0,%1,%2,%3};"
        : "+f"(d[0]), "+f"(d[1]), "+f"(d[2]), "+f"(d[3])
        : "r"(a[0]), "r"(a[1]), "r"(a[2]), "r"(a[3]), "r"(b[0]), "r"(b[1]));
}
__device__ __forceinline__ uint32_t pack_h2(float x, float y) {
    __half2 h = __floats2half2_rn(x, y);
    return *(uint32_t*)&h;
}

// ---------------------------------------------------------------------------
// fp32 -> fp16 conversion (8 elems/thread)
// ---------------------------------------------------------------------------
__global__ void cvt_h(const float* __restrict__ s, __half* __restrict__ d, size_t n)
{
    const size_t i = ((size_t)blockIdx.x * blockDim.x + threadIdx.x) * 8;
    if (i < n) {
        float4 a = *(const float4*)(s + i);
        float4 b = *(const float4*)(s + i + 4);
        uint4 o;
        o.x = pack_h2(a.x, a.y); o.y = pack_h2(a.z, a.w);
        o.z = pack_h2(b.x, b.y); o.w = pack_h2(b.z, b.w);
        *(uint4*)(d + i) = o;
    }
}

// Transpose W[K][N] -> Wt[N][K] fp16, 4 weights in one launch (z selects)
__global__ void trans_cvt4(const float* __restrict__ W0, const float* __restrict__ W1,
                           const float* __restrict__ W2, const float* __restrict__ W3,
                           __half* __restrict__ Wt)
{
    __shared__ float t[32][33];
    const int z = blockIdx.z;
    const float* W = (z == 0) ? W0 : (z == 1) ? W1 : (z == 2) ? W2 : W3;
    __half* Wo = Wt + (size_t)z * Dc * Dc;
    const int x  = blockIdx.x * 32 + threadIdx.x;   // n
    const int y0 = blockIdx.y * 32;                 // k
#pragma unroll
    for (int i = threadIdx.y; i < 32; i += 8)
        t[i][threadIdx.x] = W[(size_t)(y0 + i) * Dc + x];
    __syncthreads();
    const int xo  = blockIdx.y * 32 + threadIdx.x;  // k (out col)
    const int yo0 = blockIdx.x * 32;                // n (out row)
#pragma unroll
    for (int i = threadIdx.y; i < 32; i += 8)
        Wo[(size_t)(yo0 + i) * Dc + xo] = __float2half_rn(t[threadIdx.x][i]);
}

// ---------------------------------------------------------------------------
// GEMM (fp16 mma.sync m16n8k16): C = (A @ W + bias) * scale
// A: [M][K] fp16. Wt: [N][K] fp16 (K-major). BM=BN=128, BK=32, 3-stage.
// ---------------------------------------------------------------------------
#define GBK   32
#define GNKT  (Dc / GBK)          // 32
#define GST   20                  // uint32 row stride (16 data + 4 pad)
#define G_STAGE (128 * GST)       // 2560 u32 per tile per stage
#define GEMM_SMEM (6 * G_STAGE * 4)   // 61440 B

template<int MODE>
__device__ __forceinline__
void gemm_body(const __half* __restrict__ A, const __half* __restrict__ Wt,
               const float* __restrict__ bias, void* Cv, float scale,
               int m0, int n0)
{
    extern __shared__ uint32_t dsm[];
    uint32_t* As = dsm;
    uint32_t* Bs = dsm + 3 * G_STAGE;

    const int tid  = threadIdx.x;
    const int warp = tid >> 5;
    const int lane = tid & 31;
    const int lq   = lane >> 2;
    const int lr   = lane & 3;
    const int wm   = (warp & 3) * 32;
    const int wn   = (warp >> 2) * 64;

    const __half* Ag = A + (size_t)m0 * Dc;
    const __half* Bg = Wt + (size_t)n0 * Dc;
    const uint32_t aAddr = smem_u32(As);
    const uint32_t bAddr = smem_u32(Bs);

#define GLOAD(st, kt)                                                          \
    do {                                                                       \
        _Pragma("unroll")                                                      \
        for (int u = 0; u < 2; u++) {                                          \
            const int idx = u * 256 + tid;                                     \
            const int r = idx >> 2, c = idx & 3;                               \
            cp16(aAddr + ((st) * G_STAGE + r * GST + c * 4) * 4,               \
                 Ag + (size_t)r * Dc + (kt) * GBK + c * 8);                    \
        }                                                                      \
        _Pragma("unroll")                                                      \
        for (int u = 0; u < 2; u++) {                                          \
            const int idx = u * 256 + tid;                                     \
            const int r = idx >> 2, c = idx & 3;                               \
            cp16(bAddr + ((st) * G_STAGE + r * GST + c * 4) * 4,               \
                 Bg + (size_t)r * Dc + (kt) * GBK + c * 8);                    \
        }                                                                      \
        CP_COMMIT();                                                           \
    } while (0)

    float acc[2][8][4];
#pragma unroll
    for (int mi = 0; mi < 2; mi++)
#pragma unroll
        for (int ni = 0; ni < 8; ni++)
#pragma unroll
            for (int j = 0; j < 4; j++) acc[mi][ni][j] = 0.f;

    GLOAD(0, 0);
    GLOAD(1, 1);

    for (int kt = 0; kt < GNKT; kt++) {
        if (kt + 1 < GNKT) { CP_WAIT1(); } else { CP_WAIT0(); }
        __syncthreads();
        if (kt + 2 < GNKT) GLOAD((kt + 2) % 3, kt + 2);

        const uint32_t* Ac = As + (kt % 3) * G_STAGE;
        const uint32_t* Bn = Bs + (kt % 3) * G_STAGE;

#pragma unroll
        for (int ks = 0; ks < 2; ks++) {
            const int k0 = ks * 8;
            uint32_t a[2][4];
#pragma unroll
            for (int mi = 0; mi < 2; mi++) {
                const int r = wm + mi * 16;
                a[mi][0] = Ac[(r + lq)     * GST + k0 + lr];
                a[mi][1] = Ac[(r + 8 + lq) * GST + k0 + lr];
                a[mi][2] = Ac[(r + lq)     * GST + k0 + 4 + lr];
                a[mi][3] = Ac[(r + 8 + lq) * GST + k0 + 4 + lr];
            }
#pragma unroll
            for (int ni = 0; ni < 8; ni++) {
                uint32_t b[2];
                b[0] = Bn[(wn + ni * 8 + lq) * GST + k0 + lr];
                b[1] = Bn[(wn + ni * 8 + lq) * GST + k0 + 4 + lr];
                mma16(acc[0][ni], a[0], b);
                mma16(acc[1][ni], a[1], b);
            }
        }
    }
#undef GLOAD

#pragma unroll
    for (int mi = 0; mi < 2; mi++) {
        const int mA = m0 + wm + mi * 16 + lq;
#pragma unroll
        for (int ni = 0; ni < 8; ni++) {
            const int c = n0 + wn + ni * 8 + 2 * lr;
            const float2 bv = *(const float2*)(bias + c);
            const float v00 = (acc[mi][ni][0] + bv.x) * scale;
            const float v01 = (acc[mi][ni][1] + bv.y) * scale;
            const float v10 = (acc[mi][ni][2] + bv.x) * scale;
            const float v11 = (acc[mi][ni][3] + bv.y) * scale;
            if (MODE == 0) {
                float* C = (float*)Cv;
                *(float2*)(C + (size_t)mA * Dc + c) = make_float2(v00, v01);
                *(float2*)(C + (size_t)(mA + 8) * Dc + c) = make_float2(v10, v11);
            } else {
                __half* C = (__half*)Cv;
                const int h = c >> 6, hd = c & 63;
                const int b0i = mA >> 11, t0 = mA & 2047;
                const int b1i = (mA + 8) >> 11, t1 = (mA + 8) & 2047;
                *(uint32_t*)(C + (((size_t)(b0i * Hc + h)) * Tc + t0) * HDc + hd)
                    = pack_h2(v00, v01);
                *(uint32_t*)(C + (((size_t)(b1i * Hc + h)) * Tc + t1) * HDc + hd)
                    = pack_h2(v10, v11);
            }
        }
    }
}

__global__ __launch_bounds__(256, 2)
void gemm_qkv(const __half* __restrict__ A,
              const __half* __restrict__ W0, const __half* __restrict__ W1,
              const __half* __restrict__ W2,
              const float* __restrict__ b0, const float* __restrict__ b1,
              const float* __restrict__ b2,
              __half* __restrict__ C0, __half* __restrict__ C1,
              __half* __restrict__ C2)
{
    const int z = blockIdx.z;
    const __half* W  = (z == 0) ? W0 : (z == 1) ? W1 : W2;
    const float*  bs = (z == 0) ? b0 : (z == 1) ? b1 : b2;
    __half* C = (z == 0) ? C0 : (z == 1) ? C1 : C2;
    const float scale = (z == 0) ? SCALING : 1.0f;
    gemm_body<1>(A, W, bs, C, scale, blockIdx.y * 128, blockIdx.x * 128);
}

__global__ __launch_bounds__(256, 2)
void gemm_oproj(const __half* __restrict__ A, const __half* __restrict__ W,
                const float* __restrict__ bias, float* __restrict__ C)
{
    gemm_body<0>(A, W, bias, C, 1.0f, blockIdx.y * 128, blockIdx.x * 128);
}

// ---------------------------------------------------------------------------
// Flash attention (fp16 mma.sync). Block: 128 q-rows of one (b,h), 8 warps.
// Grid: x = head (16), y = b*16 + q-tile -> all heads of one (b,q0) run
// concurrently and share mask rows in L2. Mask is fp16.
// ---------------------------------------------------------------------------
#define FST  36
#define QS0  0
#define KS0  (128 * FST)
#define KBUF (64 * FST)
#define VS0  (KS0 + 2 * KBUF)
#define PS0  (VS0 + 2 * KBUF)
#define FA_SMEM ((PS0 + 128 * FST) * 4)   // 73728 B

extern __shared__ uint32_t smu[];

__global__ __launch_bounds__(256, 2)
void flash_tc(const __half* __restrict__ Q, const __half* __restrict__ K,
              const __half* __restrict__ V, const __half* __restrict__ Msk,
              __half* __restrict__ Out)
{
    uint32_t* Qs = smu + QS0;
    uint32_t* Ps = smu + PS0;

    const int tid  = threadIdx.x;
    const int warp = tid >> 5;
    const int lane = tid & 31;
    const int lq   = lane >> 2;
    const int lr   = lane & 3;
    const int wm   = warp * 16;
    const int sp   = tid & 31;
    const int hd0  = (tid >> 5) * 8;

    const int h  = blockIdx.x;            // head: fastest -> mask L2 reuse
    const int b  = blockIdx.y >> 4;
    const int q0 = (blockIdx.y & 15) * 128;
    const int bh = b * Hc + h;

    const __half* Qg = Q + (size_t)bh * Tc * HDc + (size_t)q0 * HDc;
    const __half* Kg = K + (size_t)bh * Tc * HDc;
    const __half* Vg = V + (size_t)bh * Tc * HDc;
    const __half* Mg = Msk + (size_t)b * Tc * Tc;

    const uint32_t qAddr = smem_u32(smu) + QS0 * 4;
    const uint32_t kAddr = smem_u32(smu) + KS0 * 4;

    // Prologue: cp.async Q + K0, LDG+transpose V0
#pragma unroll
    for (int u = 0; u < 4; u++) {
        const int idx = u * 256 + tid;
        const int r = idx >> 3, c = idx & 7;
        cp16(qAddr + (r * FST + c * 4) * 4, Qg + (size_t)r * HDc + c * 8);
    }
#pragma unroll
    for (int u = 0; u < 2; u++) {
        const int idx = u * 256 + tid;
        const int r = idx >> 3, c = idx & 7;
        cp16(kAddr + (r * FST + c * 4) * 4, Kg + (size_t)r * HDc + c * 8);
    }
    CP_COMMIT();
    {
        const uint32_t* vp = (const uint32_t*)Vg + (size_t)(2 * sp) * 32 + (hd0 >> 1);
        uint4 va = *(const uint4*)vp;
        uint4 vb = *(const uint4*)(vp + 32);
        CP_WAIT0();
        uint32_t* Vd = smu + VS0;
        const uint32_t* aw = &va.x;
        const uint32_t* bw = &vb.x;
#pragma unroll
        for (int i = 0; i < 4; i++) {
            Vd[(hd0 + 2 * i)     * FST + sp] = __byte_perm(aw[i], bw[i], 0x5410);
            Vd[(hd0 + 2 * i + 1) * FST + sp] = __byte_perm(aw[i], bw[i], 0x7632);
        }
    }
    __syncthreads();

    // Hoist Q fragments into registers (tile-invariant across KV loop)
    uint32_t qa[4][4];
#pragma unroll
    for (int ks = 0; ks < 4; ks++) {
        const int k0 = ks * 8;
        qa[ks][0] = Qs[(wm + lq)     * FST + k0 + lr];
        qa[ks][1] = Qs[(wm + 8 + lq) * FST + k0 + lr];
        qa[ks][2] = Qs[(wm + lq)     * FST + k0 + 4 + lr];
        qa[ks][3] = Qs[(wm + 8 + lq) * FST + k0 + 4 + lr];
    }

    float o[8][4];
    float mrow[2], lrow[2];
#pragma unroll
    for (int ni = 0; ni < 8; ni++)
#pragma unroll
        for (int j = 0; j < 4; j++) o[ni][j] = 0.f;
    mrow[0] = mrow[1] = -1e30f;
    lrow[0] = lrow[1] = 0.f;

    const int mrow0 = q0 + wm + lq;
    const int mrow1 = mrow0 + 8;

    for (int kb = 0; kb < Tc / 64; kb++) {
        const int cur = kb & 1;
        uint4 va, vb;
        const bool pre = (kb + 1 < Tc / 64);
        if (pre) {
#pragma unroll
            for (int u = 0; u < 2; u++) {
                const int idx = u * 256 + tid;
                const int r = idx >> 3, c = idx & 7;
                cp16(kAddr + ((1 - cur) * KBUF + r * FST + c * 4) * 4,
                     Kg + (size_t)((kb + 1) * 64 + r) * HDc + c * 8);
            }
            CP_COMMIT();
            const uint32_t* vp = (const uint32_t*)Vg
                + (size_t)((kb + 1) * 64 + 2 * sp) * 32 + (hd0 >> 1);
            va = *(const uint4*)vp;
            vb = *(const uint4*)(vp + 32);
        }

        // S init = mask (fp16 pair loads; issue early)
        float s[8][4];
#pragma unroll
        for (int ni = 0; ni < 8; ni++) {
            const int c = kb * 64 + ni * 8 + 2 * lr;
            const uint32_t mp0 = *(const uint32_t*)(Mg + (size_t)mrow0 * Tc + c);
            const uint32_t mp1 = *(const uint32_t*)(Mg + (size_t)mrow1 * Tc + c);
            const float2 m0v = __half22float2(*(const __half2*)&mp0);
            const float2 m1v = __half22float2(*(const __half2*)&mp1);
            s[ni][0] = m0v.x; s[ni][1] = m0v.y;
            s[ni][2] = m1v.x; s[ni][3] = m1v.y;
        }

        // S += Q @ K^T
        const uint32_t* Kb = smu + KS0 + cur * KBUF;
#pragma unroll
        for (int ks = 0; ks < 4; ks++) {
            const int k0 = ks * 8;
#pragma unroll
            for (int ni = 0; ni < 8; ni++) {
                uint32_t bfr[2];
                bfr[0] = Kb[(ni * 8 + lq) * FST + k0 + lr];
                bfr[1] = Kb[(ni * 8 + lq) * FST + k0 + 4 + lr];
                mma16(s[ni], qa[ks], bfr);
            }
        }

        // Online softmax
#pragma unroll
        for (int r = 0; r < 2; r++) {
            const int j0 = r * 2;
            float rmax = -1e30f;
#pragma unroll
            for (int ni = 0; ni < 8; ni++)
                rmax = fmaxf(rmax, fmaxf(s[ni][j0], s[ni][j0 + 1]));
            rmax = fmaxf(rmax, __shfl_xor_sync(0xffffffffu, rmax, 1));
            rmax = fmaxf(rmax, __shfl_xor_sync(0xffffffffu, rmax, 2));
            const float mnew = fmaxf(mrow[r], rmax);
            const float corr = __expf(mrow[r] - mnew);
            mrow[r] = mnew;
            float rs = 0.f;
#pragma unroll
            for (int ni = 0; ni < 8; ni++) {
                const float p0 = __expf(s[ni][j0]     - mnew);
                const float p1 = __expf(s[ni][j0 + 1] - mnew);
                s[ni][j0] = p0; s[ni][j0 + 1] = p1;
                rs += p0 + p1;
            }
            rs += __shfl_xor_sync(0xffffffffu, rs, 1);
            rs += __shfl_xor_sync(0xffffffffu, rs, 2);
            lrow[r] = lrow[r] * corr + rs;
#pragma unroll
            for (int ni = 0; ni < 8; ni++) {
                o[ni][j0]     *= corr;
                o[ni][j0 + 1] *= corr;
            }
        }

        // Pack P -> fp16 smem (warp-private rows)
#pragma unroll
        for (int ni = 0; ni < 8; ni++) {
            Ps[(wm + lq)     * FST + ni * 4 + lr] = pack_h2(s[ni][0], s[ni][1]);
            Ps[(wm + 8 + lq) * FST + ni * 4 + lr] = pack_h2(s[ni][2], s[ni][3]);
        }
        __syncwarp();

        // O += P @ V
        const uint32_t* Vb = smu + VS0 + cur * KBUF;
#pragma unroll
        for (int ks = 0; ks < 4; ks++) {
            const int k0 = ks * 8;
            uint32_t a[4];
            a[0] = Ps[(wm + lq)     * FST + k0 + lr];
            a[1] = Ps[(wm + 8 + lq) * FST + k0 + lr];
            a[2] = Ps[(wm + lq)     * FST + k0 + 4 + lr];
            a[3] = Ps[(wm + 8 + lq) * FST + k0 + 4 + lr];
#pragma unroll
            for (int ni = 0; ni < 8; ni++) {
                uint32_t bfr[2];
                bfr[0] = Vb[(ni * 8 + lq) * FST + k0 + lr];
                bfr[1] = Vb[(ni * 8 + lq) * FST + k0 + 4 + lr];
                mma16(o[ni], a, bfr);
            }
        }

        if (pre) {
            CP_WAIT0();
            uint32_t* Vd = smu + VS0 + (1 - cur) * KBUF;
            const uint32_t* aw = &va.x;
            const uint32_t* bw = &vb.x;
#pragma unroll
            for (int i = 0; i < 4; i++) {
                Vd[(hd0 + 2 * i)     * FST + sp] = __byte_perm(aw[i], bw[i], 0x5410);
                Vd[(hd0 + 2 * i + 1) * FST + sp] = __byte_perm(aw[i], bw[i], 0x7632);
            }
        }
        __syncthreads();
    }

    // Normalize + write fp16 [B*T, D]
    const float inv0 = 1.f / lrow[0];
    const float inv1 = 1.f / lrow[1];
    const int t0 = q0 + wm + lq;
    const int t1 = t0 + 8;
    uint32_t* Og = (uint32_t*)Out;
#pragma unroll
    for (int ni = 0; ni < 8; ni++) {
        const int cp = h * 32 + ni * 4 + lr;
        Og[((size_t)(b * Tc + t0)) * 512 + cp] = pack_h2(o[ni][0] * inv0, o[ni][1] * inv0);
        Og[((size_t)(b * Tc + t1)) * 512 + cp] = pack_h2(o[ni][2] * inv1, o[ni][3] * inv1);
    }
}

// ---------------------------------------------------------------------------
// Launch
// ---------------------------------------------------------------------------
extern "C" void kernel_launch(void* const* d_in, const int* in_sizes, int n_in,
                              void* d_out, int out_size)
{
    (void)in_sizes; (void)n_in; (void)out_size;
    const float* hs   = (const float*)d_in[0];
    const float* mask = (const float*)d_in[1];
    const float* Wq   = (const float*)d_in[2];
    const float* bq   = (const float*)d_in[3];
    const float* Wk   = (const float*)d_in[4];
    const float* bk   = (const float*)d_in[5];
    const float* Wv   = (const float*)d_in[6];
    const float* bv   = (const float*)d_in[7];
    const float* Wo   = (const float*)d_in[8];
    const float* bo   = (const float*)d_in[9];
    float* out = (float*)d_out;

    __half *q, *k, *v, *attn, *hs16, *wt, *m16;
    cudaGetSymbolAddress((void**)&q,    g_q);
    cudaGetSymbolAddress((void**)&k,    g_k);
    cudaGetSymbolAddress((void**)&v,    g_v);
    cudaGetSymbolAddress((void**)&attn, g_attn);
    cudaGetSymbolAddress((void**)&hs16, g_hs16);
    cudaGetSymbolAddress((void**)&wt,   g_wt16);
    cudaGetSymbolAddress((void**)&m16,  g_msk16);
    __half* wq16 = wt;
    __half* wk16 = wt + (size_t)Dc * Dc;
    __half* wv16 = wt + (size_t)2 * Dc * Dc;
    __half* wo16 = wt + (size_t)3 * Dc * Dc;

    cudaFuncSetAttribute(gemm_qkv,
                         cudaFuncAttributeMaxDynamicSharedMemorySize, GEMM_SMEM);
    cudaFuncSetAttribute(gemm_oproj,
                         cudaFuncAttributeMaxDynamicSharedMemorySize, GEMM_SMEM);
    cudaFuncSetAttribute(flash_tc,
                         cudaFuncAttributeMaxDynamicSharedMemorySize, FA_SMEM);

    const size_t NH = (size_t)Mc * Dc;          // 8M
    const size_t NM = (size_t)Bc * Tc * Tc;     // 16.7M
    cvt_h<<<(int)(NH / 2048), 256>>>(hs, hs16, NH);
    cvt_h<<<(int)(NM / 2048), 256>>>(mask, m16, NM);
    dim3 tb(32, 8), tg(Dc / 32, Dc / 32, 4);
    trans_cvt4<<<tg, tb>>>(Wq, Wk, Wv, Wo, wt);

    dim3 gq(Dc / 128, Mc / 128, 3);   // (8, 64, 3)
    gemm_qkv<<<gq, 256, GEMM_SMEM>>>(hs16, wq16, wk16, wv16, bq, bk, bv, q, k, v);

    dim3 ga(Hc, Bc * (Tc / 128));     // (16, 64): x=head for mask L2 reuse
    flash_tc<<<ga, 256, FA_SMEM>>>(q, k, v, m16, attn);

    dim3 gg(Dc / 128, Mc / 128);      // (8, 64)
    gemm_oproj<<<gg, 256, GEMM_SMEM>>>(attn, wo16, bo, out);
}

// round 7
// speedup vs baseline: 1.1583x; 1.1583x over previous
#include <cuda_runtime.h>
#include <cuda_fp16.h>
#include <cstdint>

// Problem constants
#define Bc   4
#define Tc   2048
#define Dc   1024
#define Hc   16
#define HDc  64
#define Mc   (Bc * Tc)          // 8192 rows
#define SCALING 0.125f

// Scratch (allocation-free rule)
__device__ __half g_q[Mc * Dc];
__device__ __half g_k[Mc * Dc];
__device__ __half g_v[Mc * Dc];
__device__ __half g_attn[Mc * Dc];
__device__ __half g_hs16[Mc * Dc];
__device__ __half g_wt16[4][Dc * Dc];
__device__ __half g_msk16[(size_t)Bc * Tc * Tc];

// ---------------------------------------------------------------------------
// Helpers
// ---------------------------------------------------------------------------
__device__ __forceinline__ uint32_t smem_u32(const void* p) {
    uint32_t a;
    asm("{ .reg .u64 t; cvta.to.shared.u64 t, %1; cvt.u32.u64 %0, t; }"
        : "=r"(a) : "l"(p));
    return a;
}
__device__ __forceinline__ void cp16(uint32_t dst, const void* src) {
    asm volatile("cp.async.cg.shared.global [%0], [%1], 16;"
                 :: "r"(dst), "l"(src) : "memory");
}
#define CP_COMMIT() asm volatile("cp.async.commit_group;" ::: "memory")
#define CP_WAIT1()  asm volatile("cp.async.wait_group 1;" ::: "memory")
#define CP_WAIT0()  asm volatile("cp.async.wait_group 0;" ::: "memory")

__device__ __forceinline__ void mma16(float* d, const uint32_t* a, const uint32_t* b) {
    asm volatile(
        "mma.sync.aligned.m16n8k16.row.col.f32.f16.f16.f32 "
        "{%0,%1,%2,%3}, {%4,%5,%6,%7}, {%8,%9}, {%0,%1,%2,%3};"
        : "+f"(d[0]), "+f"(d[1]), "+f"(d[2]), "+f"(d[3])
        : "r"(a[0]), "r"(a[1]), "r"(a[2]), "r"(a[3]), "r"(b[0]), "r"(b[1]));
}
__device__ __forceinline__ void ldsm4(uint32_t* r, uint32_t addr) {
    asm volatile("ldmatrix.sync.aligned.m8n8.x4.shared.b16 {%0,%1,%2,%3}, [%4];"
                 : "=r"(r[0]), "=r"(r[1]), "=r"(r[2]), "=r"(r[3]) : "r"(addr));
}
__device__ __forceinline__ uint32_t pack_h2(float x, float y) {
    __half2 h = __floats2half2_rn(x, y);
    return *(uint32_t*)&h;
}

// ---------------------------------------------------------------------------
// fp32 -> fp16 conversion
// ---------------------------------------------------------------------------
__global__ void cvt_h(const float* __restrict__ s, __half* __restrict__ d, size_t n)
{
    const size_t i = ((size_t)blockIdx.x * blockDim.x + threadIdx.x) * 8;
    if (i < n) {
        float4 a = *(const float4*)(s + i);
        float4 b = *(const float4*)(s + i + 4);
        uint4 o;
        o.x = pack_h2(a.x, a.y); o.y = pack_h2(a.z, a.w);
        o.z = pack_h2(b.x, b.y); o.w = pack_h2(b.z, b.w);
        *(uint4*)(d + i) = o;
    }
}

// Transpose W[K][N] -> Wt[N][K] fp16 (4 weights; z selects)
__global__ void trans_cvt4(const float* __restrict__ W0, const float* __restrict__ W1,
                           const float* __restrict__ W2, const float* __restrict__ W3,
                           __half* __restrict__ Wt)
{
    __shared__ float t[32][33];
    const int z = blockIdx.z;
    const float* W = (z == 0) ? W0 : (z == 1) ? W1 : (z == 2) ? W2 : W3;
    __half* Wo = Wt + (size_t)z * Dc * Dc;
    const int x  = blockIdx.x * 32 + threadIdx.x;
    const int y0 = blockIdx.y * 32;
#pragma unroll
    for (int i = threadIdx.y; i < 32; i += 8)
        t[i][threadIdx.x] = W[(size_t)(y0 + i) * Dc + x];
    __syncthreads();
    const int xo  = blockIdx.y * 32 + threadIdx.x;
    const int yo0 = blockIdx.x * 32;
#pragma unroll
    for (int i = threadIdx.y; i < 32; i += 8)
        Wo[(size_t)(yo0 + i) * Dc + xo] = __float2half_rn(t[threadIdx.x][i]);
}

// ---------------------------------------------------------------------------
// GEMM (fp16 mma + ldmatrix): C = (A @ W + bias) * scale
// A: [M][K] fp16. Wt: [N][K] fp16. BM=BN=128, BK=32, 3-stage cp.async.
// ---------------------------------------------------------------------------
#define GBK   32
#define GNKT  (Dc / GBK)          // 32
#define GST   20                  // u32 row stride
#define G_STAGE (128 * GST)
#define GEMM_SMEM (6 * G_STAGE * 4)   // 61440 B

template<int MODE>
__device__ __forceinline__
void gemm_body(const __half* __restrict__ A, const __half* __restrict__ Wt,
               const float* __restrict__ bias, void* Cv, float scale,
               int m0, int n0)
{
    extern __shared__ uint32_t dsm[];
    const int tid  = threadIdx.x;
    const int warp = tid >> 5;
    const int lane = tid & 31;
    const int lq   = lane >> 2;
    const int lr   = lane & 3;
    const int wm   = (warp & 3) * 32;
    const int wn   = (warp >> 2) * 64;

    const __half* Ag = A + (size_t)m0 * Dc;
    const __half* Bg = Wt + (size_t)n0 * Dc;
    const uint32_t aBase = smem_u32(dsm);
    const uint32_t bBase = aBase + 3 * G_STAGE * 4;

    // ldmatrix per-lane offsets (bytes)
    const uint32_t aOff = ((wm + (lane & 15)) * GST) * 4 + (lane >> 4) * 16;
    const uint32_t bOff = (((lane & 7) + ((lane >> 4) << 3) + wn) * GST) * 4
                        + ((lane >> 3) & 1) * 16;

#define GLOAD(st, kt)                                                          \
    do {                                                                       \
        _Pragma("unroll")                                                      \
        for (int u = 0; u < 2; u++) {                                          \
            const int idx = u * 256 + tid;                                     \
            const int r = idx >> 2, c = idx & 3;                               \
            cp16(aBase + ((st) * G_STAGE + r * GST + c * 4) * 4,               \
                 Ag + (size_t)r * Dc + (kt) * GBK + c * 8);                    \
        }                                                                      \
        _Pragma("unroll")                                                      \
        for (int u = 0; u < 2; u++) {                                          \
            const int idx = u * 256 + tid;                                     \
            const int r = idx >> 2, c = idx & 3;                               \
            cp16(bBase + ((st) * G_STAGE + r * GST + c * 4) * 4,               \
                 Bg + (size_t)r * Dc + (kt) * GBK + c * 8);                    \
        }                                                                      \
        CP_COMMIT();                                                           \
    } while (0)

    float acc[2][8][4];
#pragma unroll
    for (int mi = 0; mi < 2; mi++)
#pragma unroll
        for (int ni = 0; ni < 8; ni++)
#pragma unroll
            for (int j = 0; j < 4; j++) acc[mi][ni][j] = 0.f;

    GLOAD(0, 0);
    GLOAD(1, 1);

    for (int kt = 0; kt < GNKT; kt++) {
        if (kt + 1 < GNKT) { CP_WAIT1(); } else { CP_WAIT0(); }
        __syncthreads();
        if (kt + 2 < GNKT) GLOAD((kt + 2) % 3, kt + 2);

        const uint32_t aSt = aBase + (kt % 3) * G_STAGE * 4;
        const uint32_t bSt = bBase + (kt % 3) * G_STAGE * 4;

#pragma unroll
        for (int ks = 0; ks < 2; ks++) {
            uint32_t a[2][4];
            ldsm4(a[0], aSt + aOff + ks * 32);
            ldsm4(a[1], aSt + aOff + 16 * GST * 4 + ks * 32);
#pragma unroll
            for (int nip = 0; nip < 4; nip++) {
                uint32_t b[4];
                ldsm4(b, bSt + bOff + nip * (16 * GST * 4) + ks * 32);
                mma16(acc[0][2 * nip],     a[0], b);
                mma16(acc[1][2 * nip],     a[1], b);
                mma16(acc[0][2 * nip + 1], a[0], b + 2);
                mma16(acc[1][2 * nip + 1], a[1], b + 2);
            }
        }
    }
#undef GLOAD

#pragma unroll
    for (int mi = 0; mi < 2; mi++) {
        const int mA = m0 + wm + mi * 16 + lq;
#pragma unroll
        for (int ni = 0; ni < 8; ni++) {
            const int c = n0 + wn + ni * 8 + 2 * lr;
            const float2 bv = *(const float2*)(bias + c);
            const float v00 = (acc[mi][ni][0] + bv.x) * scale;
            const float v01 = (acc[mi][ni][1] + bv.y) * scale;
            const float v10 = (acc[mi][ni][2] + bv.x) * scale;
            const float v11 = (acc[mi][ni][3] + bv.y) * scale;
            if (MODE == 0) {
                float* C = (float*)Cv;
                *(float2*)(C + (size_t)mA * Dc + c) = make_float2(v00, v01);
                *(float2*)(C + (size_t)(mA + 8) * Dc + c) = make_float2(v10, v11);
            } else {
                __half* C = (__half*)Cv;
                const int h = c >> 6, hd = c & 63;
                const int b0i = mA >> 11, t0 = mA & 2047;
                const int b1i = (mA + 8) >> 11, t1 = (mA + 8) & 2047;
                *(uint32_t*)(C + (((size_t)(b0i * Hc + h)) * Tc + t0) * HDc + hd)
                    = pack_h2(v00, v01);
                *(uint32_t*)(C + (((size_t)(b1i * Hc + h)) * Tc + t1) * HDc + hd)
                    = pack_h2(v10, v11);
            }
        }
    }
}

__global__ __launch_bounds__(256, 2)
void gemm_qkv(const __half* __restrict__ A,
              const __half* __restrict__ W0, const __half* __restrict__ W1,
              const __half* __restrict__ W2,
              const float* __restrict__ b0, const float* __restrict__ b1,
              const float* __restrict__ b2,
              __half* __restrict__ C0, __half* __restrict__ C1,
              __half* __restrict__ C2)
{
    const int z = blockIdx.z;
    const __half* W  = (z == 0) ? W0 : (z == 1) ? W1 : W2;
    const float*  bs = (z == 0) ? b0 : (z == 1) ? b1 : b2;
    __half* C = (z == 0) ? C0 : (z == 1) ? C1 : C2;
    const float scale = (z == 0) ? SCALING : 1.0f;
    gemm_body<1>(A, W, bs, C, scale, blockIdx.y * 128, blockIdx.x * 128);
}

__global__ __launch_bounds__(256, 2)
void gemm_oproj(const __half* __restrict__ A, const __half* __restrict__ W,
                const float* __restrict__ bias, float* __restrict__ C)
{
    gemm_body<0>(A, W, bias, C, 1.0f, blockIdx.y * 128, blockIdx.x * 128);
}

// ---------------------------------------------------------------------------
// Flash attention: fp16 mma + ldmatrix + register-resident P (no smem P).
// Block: 128 q-rows of one (b,h), 8 warps. KV tiles 64, double buffered.
// ---------------------------------------------------------------------------
#define FST  36
#define QS0  0
#define KS0  (128 * FST)
#define KBUF (64 * FST)
#define VS0  (KS0 + 2 * KBUF)
#define FA_SMEM ((VS0 + 2 * KBUF) * 4)   // 55296 B

extern __shared__ uint32_t smu[];

__global__ __launch_bounds__(256, 2)
void flash_tc(const __half* __restrict__ Q, const __half* __restrict__ K,
              const __half* __restrict__ V, const __half* __restrict__ Msk,
              __half* __restrict__ Out)
{
    const int tid  = threadIdx.x;
    const int warp = tid >> 5;
    const int lane = tid & 31;
    const int lq   = lane >> 2;
    const int lr   = lane & 3;
    const int wm   = warp * 16;
    const int sp   = tid & 31;
    const int hd0  = (tid >> 5) * 8;

    const int h  = blockIdx.x;
    const int b  = blockIdx.y >> 4;
    const int q0 = (blockIdx.y & 15) * 128;
    const int bh = b * Hc + h;

    const __half* Qg = Q + (size_t)bh * Tc * HDc + (size_t)q0 * HDc;
    const __half* Kg = K + (size_t)bh * Tc * HDc;
    const __half* Vg = V + (size_t)bh * Tc * HDc;
    const __half* Mg = Msk + (size_t)b * Tc * Tc;

    const uint32_t base  = smem_u32(smu);
    const uint32_t qBase = base;
    const uint32_t kBase = base + KS0 * 4;
    const uint32_t vBase = base + VS0 * 4;

    // ldmatrix per-lane offsets (bytes)
    const uint32_t qOff  = ((wm + (lane & 15)) * FST) * 4 + (lane >> 4) * 16;
    const uint32_t bfOff = (((lane & 7) + ((lane >> 4) << 3)) * FST) * 4
                         + ((lane >> 3) & 1) * 16;

    // Prologue: cp.async Q + K0, LDG+transpose V0
#pragma unroll
    for (int u = 0; u < 4; u++) {
        const int idx = u * 256 + tid;
        const int r = idx >> 3, c = idx & 7;
        cp16(qBase + (r * FST + c * 4) * 4, Qg + (size_t)r * HDc + c * 8);
    }
#pragma unroll
    for (int u = 0; u < 2; u++) {
        const int idx = u * 256 + tid;
        const int r = idx >> 3, c = idx & 7;
        cp16(kBase + (r * FST + c * 4) * 4, Kg + (size_t)r * HDc + c * 8);
    }
    CP_COMMIT();
    {
        const uint32_t* vp = (const uint32_t*)Vg + (size_t)(2 * sp) * 32 + (hd0 >> 1);
        uint4 va = *(const uint4*)vp;
        uint4 vb = *(const uint4*)(vp + 32);
        CP_WAIT0();
        uint32_t* Vd = smu + VS0;
        const uint32_t* aw = &va.x;
        const uint32_t* bw = &vb.x;
#pragma unroll
        for (int i = 0; i < 4; i++) {
            Vd[(hd0 + 2 * i)     * FST + sp] = __byte_perm(aw[i], bw[i], 0x5410);
            Vd[(hd0 + 2 * i + 1) * FST + sp] = __byte_perm(aw[i], bw[i], 0x7632);
        }
    }
    __syncthreads();

    // Hoist Q fragments (ldmatrix; tile-invariant)
    uint32_t qa[4][4];
#pragma unroll
    for (int ks = 0; ks < 4; ks++)
        ldsm4(qa[ks], qBase + qOff + ks * 32);

    float o[8][4];
    float mrow[2], lrow[2];
#pragma unroll
    for (int ni = 0; ni < 8; ni++)
#pragma unroll
        for (int j = 0; j < 4; j++) o[ni][j] = 0.f;
    mrow[0] = mrow[1] = -1e30f;
    lrow[0] = lrow[1] = 0.f;

    const int mrow0 = q0 + wm + lq;
    const int mrow1 = mrow0 + 8;

    for (int kb = 0; kb < Tc / 64; kb++) {
        const int cur = kb & 1;
        uint4 va, vb;
        const bool pre = (kb + 1 < Tc / 64);
        if (pre) {
#pragma unroll
            for (int u = 0; u < 2; u++) {
                const int idx = u * 256 + tid;
                const int r = idx >> 3, c = idx & 7;
                cp16(kBase + ((1 - cur) * KBUF + r * FST + c * 4) * 4,
                     Kg + (size_t)((kb + 1) * 64 + r) * HDc + c * 8);
            }
            CP_COMMIT();
            const uint32_t* vp = (const uint32_t*)Vg
                + (size_t)((kb + 1) * 64 + 2 * sp) * 32 + (hd0 >> 1);
            va = *(const uint4*)vp;
            vb = *(const uint4*)(vp + 32);
        }

        // S init = mask
        float s[8][4];
#pragma unroll
        for (int ni = 0; ni < 8; ni++) {
            const int c = kb * 64 + ni * 8 + 2 * lr;
            const uint32_t mp0 = *(const uint32_t*)(Mg + (size_t)mrow0 * Tc + c);
            const uint32_t mp1 = *(const uint32_t*)(Mg + (size_t)mrow1 * Tc + c);
            const float2 m0v = __half22float2(*(const __half2*)&mp0);
            const float2 m1v = __half22float2(*(const __half2*)&mp1);
            s[ni][0] = m0v.x; s[ni][1] = m0v.y;
            s[ni][2] = m1v.x; s[ni][3] = m1v.y;
        }

        // S += Q @ K^T  (ldmatrix K)
        const uint32_t kSt = kBase + cur * KBUF * 4;
#pragma unroll
        for (int ks = 0; ks < 4; ks++) {
#pragma unroll
            for (int nip = 0; nip < 4; nip++) {
                uint32_t bk[4];
                ldsm4(bk, kSt + bfOff + nip * (16 * FST * 4) + ks * 32);
                mma16(s[2 * nip],     qa[ks], bk);
                mma16(s[2 * nip + 1], qa[ks], bk + 2);
            }
        }

        // Online softmax
#pragma unroll
        for (int r = 0; r < 2; r++) {
            const int j0 = r * 2;
            float rmax = -1e30f;
#pragma unroll
            for (int ni = 0; ni < 8; ni++)
                rmax = fmaxf(rmax, fmaxf(s[ni][j0], s[ni][j0 + 1]));
            rmax = fmaxf(rmax, __shfl_xor_sync(0xffffffffu, rmax, 1));
            rmax = fmaxf(rmax, __shfl_xor_sync(0xffffffffu, rmax, 2));
            const float mnew = fmaxf(mrow[r], rmax);
            const float corr = __expf(mrow[r] - mnew);
            mrow[r] = mnew;
            float rs = 0.f;
#pragma unroll
            for (int ni = 0; ni < 8; ni++) {
                const float p0 = __expf(s[ni][j0]     - mnew);
                const float p1 = __expf(s[ni][j0 + 1] - mnew);
                s[ni][j0] = p0; s[ni][j0 + 1] = p1;
                rs += p0 + p1;
            }
            rs += __shfl_xor_sync(0xffffffffu, rs, 1);
            rs += __shfl_xor_sync(0xffffffffu, rs, 2);
            lrow[r] = lrow[r] * corr + rs;
#pragma unroll
            for (int ni = 0; ni < 8; ni++) {
                o[ni][j0]     *= corr;
                o[ni][j0 + 1] *= corr;
            }
        }

        // O += P @ V : P stays in registers (S-frag == A-frag layout)
        const uint32_t vSt = vBase + cur * KBUF * 4;
#pragma unroll
        for (int ks = 0; ks < 4; ks++) {
            uint32_t a[4];
            a[0] = pack_h2(s[2 * ks][0],     s[2 * ks][1]);
            a[1] = pack_h2(s[2 * ks][2],     s[2 * ks][3]);
            a[2] = pack_h2(s[2 * ks + 1][0], s[2 * ks + 1][1]);
            a[3] = pack_h2(s[2 * ks + 1][2], s[2 * ks + 1][3]);
#pragma unroll
            for (int nip = 0; nip < 4; nip++) {
                uint32_t bv2[4];
                ldsm4(bv2, vSt + bfOff + nip * (16 * FST * 4) + ks * 32);
                mma16(o[2 * nip],     a, bv2);
                mma16(o[2 * nip + 1], a, bv2 + 2);
            }
        }

        if (pre) {
            CP_WAIT0();
            uint32_t* Vd = smu + VS0 + (1 - cur) * KBUF;
            const uint32_t* aw = &va.x;
            const uint32_t* bw = &vb.x;
#pragma unroll
            for (int i = 0; i < 4; i++) {
                Vd[(hd0 + 2 * i)     * FST + sp] = __byte_perm(aw[i], bw[i], 0x5410);
                Vd[(hd0 + 2 * i + 1) * FST + sp] = __byte_perm(aw[i], bw[i], 0x7632);
            }
        }
        __syncthreads();
    }

    // Normalize + write fp16 [B*T, D]
    const float inv0 = 1.f / lrow[0];
    const float inv1 = 1.f / lrow[1];
    const int t0 = q0 + wm + lq;
    const int t1 = t0 + 8;
    uint32_t* Og = (uint32_t*)Out;
#pragma unroll
    for (int ni = 0; ni < 8; ni++) {
        const int cp = h * 32 + ni * 4 + lr;
        Og[((size_t)(b * Tc + t0)) * 512 + cp] = pack_h2(o[ni][0] * inv0, o[ni][1] * inv0);
        Og[((size_t)(b * Tc + t1)) * 512 + cp] = pack_h2(o[ni][2] * inv1, o[ni][3] * inv1);
    }
}

// ---------------------------------------------------------------------------
// Launch
// ---------------------------------------------------------------------------
extern "C" void kernel_launch(void* const* d_in, const int* in_sizes, int n_in,
                              void* d_out, int out_size)
{
    (void)in_sizes; (void)n_in; (void)out_size;
    const float* hs   = (const float*)d_in[0];
    const float* mask = (const float*)d_in[1];
    const float* Wq   = (const float*)d_in[2];
    const float* bq   = (const float*)d_in[3];
    const float* Wk   = (const float*)d_in[4];
    const float* bk   = (const float*)d_in[5];
    const float* Wv   = (const float*)d_in[6];
    const float* bv   = (const float*)d_in[7];
    const float* Wo   = (const float*)d_in[8];
    const float* bo   = (const float*)d_in[9];
    float* out = (float*)d_out;

    __half *q, *k, *v, *attn, *hs16, *wt, *m16;
    cudaGetSymbolAddress((void**)&q,    g_q);
    cudaGetSymbolAddress((void**)&k,    g_k);
    cudaGetSymbolAddress((void**)&v,    g_v);
    cudaGetSymbolAddress((void**)&attn, g_attn);
    cudaGetSymbolAddress((void**)&hs16, g_hs16);
    cudaGetSymbolAddress((void**)&wt,   g_wt16);
    cudaGetSymbolAddress((void**)&m16,  g_msk16);
    __half* wq16 = wt;
    __half* wk16 = wt + (size_t)Dc * Dc;
    __half* wv16 = wt + (size_t)2 * Dc * Dc;
    __half* wo16 = wt + (size_t)3 * Dc * Dc;

    cudaFuncSetAttribute(gemm_qkv,
                         cudaFuncAttributeMaxDynamicSharedMemorySize, GEMM_SMEM);
    cudaFuncSetAttribute(gemm_oproj,
                         cudaFuncAttributeMaxDynamicSharedMemorySize, GEMM_SMEM);
    cudaFuncSetAttribute(flash_tc,
                         cudaFuncAttributeMaxDynamicSharedMemorySize, FA_SMEM);

    const size_t NH = (size_t)Mc * Dc;
    const size_t NM = (size_t)Bc * Tc * Tc;
    cvt_h<<<(int)(NH / 2048), 256>>>(hs, hs16, NH);
    cvt_h<<<(int)(NM / 2048), 256>>>(mask, m16, NM);
    dim3 tb(32, 8), tg(Dc / 32, Dc / 32, 4);
    trans_cvt4<<<tg, tb>>>(Wq, Wk, Wv, Wo, wt);

    dim3 gq(Dc / 128, Mc / 128, 3);
    gemm_qkv<<<gq, 256, GEMM_SMEM>>>(hs16, wq16, wk16, wv16, bq, bk, bv, q, k, v);

    dim3 ga(Hc, Bc * (Tc / 128));
    flash_tc<<<ga, 256, FA_SMEM>>>(q, k, v, m16, attn);

    dim3 gg(Dc / 128, Mc / 128);
    gemm_oproj<<<gg, 256, GEMM_SMEM>>>(attn, wo16, bo, out);
}

// round 8
// speedup vs baseline: 1.3436x; 1.1600x over previous
#include <cuda_runtime.h>
#include <cuda_fp16.h>
#include <cstdint>

// Problem constants
#define Bc   4
#define Tc   2048
#define Dc   1024
#define Hc   16
#define HDc  64
#define Mc   (Bc * Tc)          // 8192 rows
#define SCALING 0.125f
#define L2E  1.4426950408889634f

// Scratch (allocation-free rule)
__device__ __half g_q[Mc * Dc];        // [B,H,T,Hd]
__device__ __half g_k[Mc * Dc];        // [B,H,T,Hd]
__device__ __half g_vt[Mc * Dc];       // [B,H,Hd,T]  (transposed!)
__device__ __half g_attn[Mc * Dc];     // [B*T, D]
__device__ __half g_hs16[Mc * Dc];
__device__ __half g_wt16[4][Dc * Dc];
__device__ __half g_msk16[(size_t)Bc * Tc * Tc];

// ---------------------------------------------------------------------------
// Helpers
// ---------------------------------------------------------------------------
__device__ __forceinline__ uint32_t smem_u32(const void* p) {
    uint32_t a;
    asm("{ .reg .u64 t; cvta.to.shared.u64 t, %1; cvt.u32.u64 %0, t; }"
        : "=r"(a) : "l"(p));
    return a;
}
__device__ __forceinline__ void cp16(uint32_t dst, const void* src) {
    asm volatile("cp.async.cg.shared.global [%0], [%1], 16;"
                 :: "r"(dst), "l"(src) : "memory");
}
#define CP_COMMIT() asm volatile("cp.async.commit_group;" ::: "memory")
#define CP_WAIT2()  asm volatile("cp.async.wait_group 2;" ::: "memory")
#define CP_WAIT0()  asm volatile("cp.async.wait_group 0;" ::: "memory")

__device__ __forceinline__ void mma16(float* d, const uint32_t* a, const uint32_t* b) {
    asm volatile(
        "mma.sync.aligned.m16n8k16.row.col.f32.f16.f16.f32 "
        "{%0,%1,%2,%3}, {%4,%5,%6,%7}, {%8,%9}, {%0,%1,%2,%3};"
        : "+f"(d[0]), "+f"(d[1]), "+f"(d[2]), "+f"(d[3])
        : "r"(a[0]), "r"(a[1]), "r"(a[2]), "r"(a[3]), "r"(b[0]), "r"(b[1]));
}
__device__ __forceinline__ void ldsm4(uint32_t* r, uint32_t addr) {
    asm volatile("ldmatrix.sync.aligned.m8n8.x4.shared.b16 {%0,%1,%2,%3}, [%4];"
                 : "=r"(r[0]), "=r"(r[1]), "=r"(r[2]), "=r"(r[3]) : "r"(addr));
}
__device__ __forceinline__ uint32_t pack_h2(float x, float y) {
    __half2 h = __floats2half2_rn(x, y);
    return *(uint32_t*)&h;
}
__device__ __forceinline__ uint32_t h2exp2_(uint32_t x) {
    uint32_t r; asm("ex2.approx.f16x2 %0, %1;" : "=r"(r) : "r"(x)); return r;
}

// ---------------------------------------------------------------------------
// fp32 -> fp16 conversion
// ---------------------------------------------------------------------------
__global__ void cvt_h(const float* __restrict__ s, __half* __restrict__ d, size_t n)
{
    const size_t i = ((size_t)blockIdx.x * blockDim.x + threadIdx.x) * 8;
    if (i < n) {
        float4 a = *(const float4*)(s + i);
        float4 b = *(const float4*)(s + i + 4);
        uint4 o;
        o.x = pack_h2(a.x, a.y); o.y = pack_h2(a.z, a.w);
        o.z = pack_h2(b.x, b.y); o.w = pack_h2(b.z, b.w);
        *(uint4*)(d + i) = o;
    }
}

// Transpose W[K][N] -> Wt[N][K] fp16 (4 weights; z selects)
__global__ void trans_cvt4(const float* __restrict__ W0, const float* __restrict__ W1,
                           const float* __restrict__ W2, const float* __restrict__ W3,
                           __half* __restrict__ Wt)
{
    __shared__ float t[32][33];
    const int z = blockIdx.z;
    const float* W = (z == 0) ? W0 : (z == 1) ? W1 : (z == 2) ? W2 : W3;
    __half* Wo = Wt + (size_t)z * Dc * Dc;
    const int x  = blockIdx.x * 32 + threadIdx.x;
    const int y0 = blockIdx.y * 32;
#pragma unroll
    for (int i = threadIdx.y; i < 32; i += 8)
        t[i][threadIdx.x] = W[(size_t)(y0 + i) * Dc + x];
    __syncthreads();
    const int xo  = blockIdx.y * 32 + threadIdx.x;
    const int yo0 = blockIdx.x * 32;
#pragma unroll
    for (int i = threadIdx.y; i < 32; i += 8)
        Wo[(size_t)(yo0 + i) * Dc + xo] = __float2half_rn(t[threadIdx.x][i]);
}

// ---------------------------------------------------------------------------
// GEMM (fp16 mma + ldmatrix): C = (A @ W + bias) * scale
// MODE 0: fp32 row-major. MODE 1: fp16 [B,H,T,Hd]. MODE 2: fp16 [B,H,Hd,T].
// BM=BN=128, BK=32, 4-stage cp.async pipeline.
// ---------------------------------------------------------------------------
#define GBK   32
#define GNKT  (Dc / GBK)          // 32
#define GST   20
#define G_STAGE (128 * GST)
#define GEMM_SMEM (8 * G_STAGE * 4)   // 81920 B

template<int MODE>
__device__ __forceinline__
void gemm_body(const __half* __restrict__ A, const __half* __restrict__ Wt,
               const float* __restrict__ bias, void* Cv, float scale,
               int m0, int n0)
{
    extern __shared__ uint32_t dsm[];
    const int tid  = threadIdx.x;
    const int warp = tid >> 5;
    const int lane = tid & 31;
    const int lq   = lane >> 2;
    const int lr   = lane & 3;
    const int wm   = (warp & 3) * 32;
    const int wn   = (warp >> 2) * 64;

    const __half* Ag = A + (size_t)m0 * Dc;
    const __half* Bg = Wt + (size_t)n0 * Dc;
    const uint32_t aBase = smem_u32(dsm);
    const uint32_t bBase = aBase + 4 * G_STAGE * 4;

    const uint32_t aOff = ((wm + (lane & 15)) * GST) * 4 + (lane >> 4) * 16;
    const uint32_t bOff = (((lane & 7) + ((lane >> 4) << 3) + wn) * GST) * 4
                        + ((lane >> 3) & 1) * 16;

#define GLOAD(st, kt)                                                          \
    do {                                                                       \
        _Pragma("unroll")                                                      \
        for (int u = 0; u < 2; u++) {                                          \
            const int idx = u * 256 + tid;                                     \
            const int r = idx >> 2, c = idx & 3;                               \
            cp16(aBase + ((st) * G_STAGE + r * GST + c * 4) * 4,               \
                 Ag + (size_t)r * Dc + (kt) * GBK + c * 8);                    \
        }                                                                      \
        _Pragma("unroll")                                                      \
        for (int u = 0; u < 2; u++) {                                          \
            const int idx = u * 256 + tid;                                     \
            const int r = idx >> 2, c = idx & 3;                               \
            cp16(bBase + ((st) * G_STAGE + r * GST + c * 4) * 4,               \
                 Bg + (size_t)r * Dc + (kt) * GBK + c * 8);                    \
        }                                                                      \
    } while (0)

    float acc[2][8][4];
#pragma unroll
    for (int mi = 0; mi < 2; mi++)
#pragma unroll
        for (int ni = 0; ni < 8; ni++)
#pragma unroll
            for (int j = 0; j < 4; j++) acc[mi][ni][j] = 0.f;

    GLOAD(0, 0); CP_COMMIT();
    GLOAD(1, 1); CP_COMMIT();
    GLOAD(2, 2); CP_COMMIT();

    for (int kt = 0; kt < GNKT; kt++) {
        CP_WAIT2();
        __syncthreads();
        if (kt + 3 < GNKT) GLOAD((kt + 3) & 3, kt + 3);
        CP_COMMIT();

        const uint32_t aSt = aBase + (kt & 3) * G_STAGE * 4;
        const uint32_t bSt = bBase + (kt & 3) * G_STAGE * 4;

#pragma unroll
        for (int ks = 0; ks < 2; ks++) {
            uint32_t a[2][4];
            ldsm4(a[0], aSt + aOff + ks * 32);
            ldsm4(a[1], aSt + aOff + 16 * GST * 4 + ks * 32);
#pragma unroll
            for (int nip = 0; nip < 4; nip++) {
                uint32_t b[4];
                ldsm4(b, bSt + bOff + nip * (16 * GST * 4) + ks * 32);
                mma16(acc[0][2 * nip],     a[0], b);
                mma16(acc[1][2 * nip],     a[1], b);
                mma16(acc[0][2 * nip + 1], a[0], b + 2);
                mma16(acc[1][2 * nip + 1], a[1], b + 2);
            }
        }
    }
#undef GLOAD

#pragma unroll
    for (int mi = 0; mi < 2; mi++) {
        const int mA = m0 + wm + mi * 16 + lq;
#pragma unroll
        for (int ni = 0; ni < 8; ni++) {
            const int c = n0 + wn + ni * 8 + 2 * lr;
            const float2 bv = *(const float2*)(bias + c);
            const float v00 = (acc[mi][ni][0] + bv.x) * scale;
            const float v01 = (acc[mi][ni][1] + bv.y) * scale;
            const float v10 = (acc[mi][ni][2] + bv.x) * scale;
            const float v11 = (acc[mi][ni][3] + bv.y) * scale;
            const int h = c >> 6, hd = c & 63;
            const int b0i = mA >> 11, t0 = mA & 2047;
            const int b1i = (mA + 8) >> 11, t1 = (mA + 8) & 2047;
            if (MODE == 0) {
                float* C = (float*)Cv;
                *(float2*)(C + (size_t)mA * Dc + c) = make_float2(v00, v01);
                *(float2*)(C + (size_t)(mA + 8) * Dc + c) = make_float2(v10, v11);
            } else if (MODE == 1) {
                __half* C = (__half*)Cv;
                *(uint32_t*)(C + (((size_t)(b0i * Hc + h)) * Tc + t0) * HDc + hd)
                    = pack_h2(v00, v01);
                *(uint32_t*)(C + (((size_t)(b1i * Hc + h)) * Tc + t1) * HDc + hd)
                    = pack_h2(v10, v11);
            } else {
                // V transposed: [B,H,Hd,T]
                __half* C = (__half*)Cv;
                const size_t r0 = ((size_t)(b0i * Hc + h)) * HDc;
                const size_t r1 = ((size_t)(b1i * Hc + h)) * HDc;
                C[(r0 + hd)     * Tc + t0] = __float2half_rn(v00);
                C[(r0 + hd + 1) * Tc + t0] = __float2half_rn(v01);
                C[(r1 + hd)     * Tc + t1] = __float2half_rn(v10);
                C[(r1 + hd + 1) * Tc + t1] = __float2half_rn(v11);
            }
        }
    }
}

__global__ __launch_bounds__(256, 2)
void gemm_qkv(const __half* __restrict__ A,
              const __half* __restrict__ W0, const __half* __restrict__ W1,
              const __half* __restrict__ W2,
              const float* __restrict__ b0, const float* __restrict__ b1,
              const float* __restrict__ b2,
              __half* __restrict__ C0, __half* __restrict__ C1,
              __half* __restrict__ C2)
{
    const int z = blockIdx.z;
    if (z == 0)      gemm_body<1>(A, W0, b0, C0, SCALING, blockIdx.y * 128, blockIdx.x * 128);
    else if (z == 1) gemm_body<1>(A, W1, b1, C1, 1.0f,    blockIdx.y * 128, blockIdx.x * 128);
    else             gemm_body<2>(A, W2, b2, C2, 1.0f,    blockIdx.y * 128, blockIdx.x * 128);
}

__global__ __launch_bounds__(256, 2)
void gemm_oproj(const __half* __restrict__ A, const __half* __restrict__ W,
                const float* __restrict__ bias, float* __restrict__ C)
{
    gemm_body<0>(A, W, bias, C, 1.0f, blockIdx.y * 128, blockIdx.x * 128);
}

// ---------------------------------------------------------------------------
// Flash attention: fp16 mma + ldmatrix, register P, h2exp softmax,
// l via ones-column MMA. V pre-transposed [B,H,Hd,T] -> cp.async like K.
// ---------------------------------------------------------------------------
#define FST  36
#define QS0  0
#define KS0  (128 * FST)
#define KBUF (64 * FST)
#define VS0  (KS0 + 2 * KBUF)
#define FA_SMEM ((VS0 + 2 * KBUF) * 4)   // 55296 B

extern __shared__ uint32_t smu[];

__global__ __launch_bounds__(256, 2)
void flash_tc(const __half* __restrict__ Q, const __half* __restrict__ K,
              const __half* __restrict__ Vt, const __half* __restrict__ Msk,
              __half* __restrict__ Out)
{
    const int tid  = threadIdx.x;
    const int warp = tid >> 5;
    const int lane = tid & 31;
    const int lq   = lane >> 2;
    const int lr   = lane & 3;
    const int wm   = warp * 16;

    const int h  = blockIdx.x;
    const int b  = blockIdx.y >> 4;
    const int q0 = (blockIdx.y & 15) * 128;
    const int bh = b * Hc + h;

    const __half* Qg = Q  + (size_t)bh * Tc * HDc + (size_t)q0 * HDc;
    const __half* Kg = K  + (size_t)bh * Tc * HDc;
    const __half* Vg = Vt + (size_t)bh * HDc * Tc;   // rows hd, cols t
    const __half* Mg = Msk + (size_t)b * Tc * Tc;

    const uint32_t base  = smem_u32(smu);
    const uint32_t qBase = base;
    const uint32_t kBase = base + KS0 * 4;
    const uint32_t vBase = base + VS0 * 4;

    const uint32_t qOff  = ((wm + (lane & 15)) * FST) * 4 + (lane >> 4) * 16;
    const uint32_t bfOff = (((lane & 7) + ((lane >> 4) << 3)) * FST) * 4
                         + ((lane >> 3) & 1) * 16;

    // Prologue: Q + K0 + V0 via cp.async
#pragma unroll
    for (int u = 0; u < 4; u++) {
        const int idx = u * 256 + tid;
        const int r = idx >> 3, c = idx & 7;
        cp16(qBase + (r * FST + c * 4) * 4, Qg + (size_t)r * HDc + c * 8);
    }
#pragma unroll
    for (int u = 0; u < 2; u++) {
        const int idx = u * 256 + tid;
        const int r = idx >> 3, c = idx & 7;
        cp16(kBase + (r * FST + c * 4) * 4, Kg + (size_t)r * HDc + c * 8);
        cp16(vBase + (r * FST + c * 4) * 4, Vg + (size_t)r * Tc + c * 8);
    }
    CP_COMMIT();
    CP_WAIT0();
    __syncthreads();

    // Q fragments (tile-invariant)
    uint32_t qa[4][4];
#pragma unroll
    for (int ks = 0; ks < 4; ks++)
        ldsm4(qa[ks], qBase + qOff + ks * 32);

    float o[8][4];
    float o_l[4] = {0.f, 0.f, 0.f, 0.f};   // l accumulator (ones-column)
    float mrow[2];
#pragma unroll
    for (int ni = 0; ni < 8; ni++)
#pragma unroll
        for (int j = 0; j < 4; j++) o[ni][j] = 0.f;
    mrow[0] = mrow[1] = -1e30f;

    const uint32_t ones2 = 0x3C003C00u;
    const uint32_t bOnes[2] = {ones2, ones2};

    const int mrow0 = q0 + wm + lq;
    const int mrow1 = mrow0 + 8;

    for (int kb = 0; kb < Tc / 64; kb++) {
        const int cur = kb & 1;
        const bool pre = (kb + 1 < Tc / 64);
        if (pre) {
#pragma unroll
            for (int u = 0; u < 2; u++) {
                const int idx = u * 256 + tid;
                const int r = idx >> 3, c = idx & 7;
                cp16(kBase + ((1 - cur) * KBUF + r * FST + c * 4) * 4,
                     Kg + (size_t)((kb + 1) * 64 + r) * HDc + c * 8);
                cp16(vBase + ((1 - cur) * KBUF + r * FST + c * 4) * 4,
                     Vg + (size_t)r * Tc + (kb + 1) * 64 + c * 8);
            }
            CP_COMMIT();
        }

        // S init = mask
        float s[8][4];
#pragma unroll
        for (int ni = 0; ni < 8; ni++) {
            const int c = kb * 64 + ni * 8 + 2 * lr;
            const uint32_t mp0 = *(const uint32_t*)(Mg + (size_t)mrow0 * Tc + c);
            const uint32_t mp1 = *(const uint32_t*)(Mg + (size_t)mrow1 * Tc + c);
            const float2 m0v = __half22float2(*(const __half2*)&mp0);
            const float2 m1v = __half22float2(*(const __half2*)&mp1);
            s[ni][0] = m0v.x; s[ni][1] = m0v.y;
            s[ni][2] = m1v.x; s[ni][3] = m1v.y;
        }

        // S += Q @ K^T
        const uint32_t kSt = kBase + cur * KBUF * 4;
#pragma unroll
        for (int ks = 0; ks < 4; ks++) {
#pragma unroll
            for (int nip = 0; nip < 4; nip++) {
                uint32_t bk[4];
                ldsm4(bk, kSt + bfOff + nip * (16 * FST * 4) + ks * 32);
                mma16(s[2 * nip],     qa[ks], bk);
                mma16(s[2 * nip + 1], qa[ks], bk + 2);
            }
        }

        // Online softmax: P = exp2((s - m) * log2e) in packed fp16
        uint32_t pp[8][2];
#pragma unroll
        for (int r = 0; r < 2; r++) {
            const int j0 = r * 2;
            float rmax = -1e30f;
#pragma unroll
            for (int ni = 0; ni < 8; ni++)
                rmax = fmaxf(rmax, fmaxf(s[ni][j0], s[ni][j0 + 1]));
            rmax = fmaxf(rmax, __shfl_xor_sync(0xffffffffu, rmax, 1));
            rmax = fmaxf(rmax, __shfl_xor_sync(0xffffffffu, rmax, 2));
            const float mnew = fmaxf(mrow[r], rmax);
            const float corr = __expf(mrow[r] - mnew);
            mrow[r] = mnew;
            const float m2 = mnew * L2E;
#pragma unroll
            for (int ni = 0; ni < 8; ni++) {
                pp[ni][r] = h2exp2_(pack_h2(fmaf(s[ni][j0],     L2E, -m2),
                                            fmaf(s[ni][j0 + 1], L2E, -m2)));
            }
#pragma unroll
            for (int ni = 0; ni < 8; ni++) {
                o[ni][j0]     *= corr;
                o[ni][j0 + 1] *= corr;
            }
            o_l[j0]     *= corr;
            o_l[j0 + 1] *= corr;
        }

        // O += P @ V ; l += P @ ones
        const uint32_t vSt = vBase + cur * KBUF * 4;
#pragma unroll
        for (int ks = 0; ks < 4; ks++) {
            uint32_t a[4];
            a[0] = pp[2 * ks][0];
            a[1] = pp[2 * ks][1];
            a[2] = pp[2 * ks + 1][0];
            a[3] = pp[2 * ks + 1][1];
#pragma unroll
            for (int nip = 0; nip < 4; nip++) {
                uint32_t bv2[4];
                ldsm4(bv2, vSt + bfOff + nip * (16 * FST * 4) + ks * 32);
                mma16(o[2 * nip],     a, bv2);
                mma16(o[2 * nip + 1], a, bv2 + 2);
            }
            mma16(o_l, a, bOnes);
        }

        if (pre) CP_WAIT0();
        __syncthreads();
    }

    // Normalize + write fp16 [B*T, D]
    const float inv0 = 1.f / o_l[0];
    const float inv1 = 1.f / o_l[2];
    const int t0 = q0 + wm + lq;
    const int t1 = t0 + 8;
    uint32_t* Og = (uint32_t*)Out;
#pragma unroll
    for (int ni = 0; ni < 8; ni++) {
        const int cp = h * 32 + ni * 4 + lr;
        Og[((size_t)(b * Tc + t0)) * 512 + cp] = pack_h2(o[ni][0] * inv0, o[ni][1] * inv0);
        Og[((size_t)(b * Tc + t1)) * 512 + cp] = pack_h2(o[ni][2] * inv1, o[ni][3] * inv1);
    }
}

// ---------------------------------------------------------------------------
// Launch
// ---------------------------------------------------------------------------
extern "C" void kernel_launch(void* const* d_in, const int* in_sizes, int n_in,
                              void* d_out, int out_size)
{
    (void)in_sizes; (void)n_in; (void)out_size;
    const float* hs   = (const float*)d_in[0];
    const float* mask = (const float*)d_in[1];
    const float* Wq   = (const float*)d_in[2];
    const float* bq   = (const float*)d_in[3];
    const float* Wk   = (const float*)d_in[4];
    const float* bk   = (const float*)d_in[5];
    const float* Wv   = (const float*)d_in[6];
    const float* bv   = (const float*)d_in[7];
    const float* Wo   = (const float*)d_in[8];
    const float* bo   = (const float*)d_in[9];
    float* out = (float*)d_out;

    __half *q, *k, *vt, *attn, *hs16, *wt, *m16;
    cudaGetSymbolAddress((void**)&q,    g_q);
    cudaGetSymbolAddress((void**)&k,    g_k);
    cudaGetSymbolAddress((void**)&vt,   g_vt);
    cudaGetSymbolAddress((void**)&attn, g_attn);
    cudaGetSymbolAddress((void**)&hs16, g_hs16);
    cudaGetSymbolAddress((void**)&wt,   g_wt16);
    cudaGetSymbolAddress((void**)&m16,  g_msk16);
    __half* wq16 = wt;
    __half* wk16 = wt + (size_t)Dc * Dc;
    __half* wv16 = wt + (size_t)2 * Dc * Dc;
    __half* wo16 = wt + (size_t)3 * Dc * Dc;

    cudaFuncSetAttribute(gemm_qkv,
                         cudaFuncAttributeMaxDynamicSharedMemorySize, GEMM_SMEM);
    cudaFuncSetAttribute(gemm_oproj,
                         cudaFuncAttributeMaxDynamicSharedMemorySize, GEMM_SMEM);
    cudaFuncSetAttribute(flash_tc,
                         cudaFuncAttributeMaxDynamicSharedMemorySize, FA_SMEM);

    const size_t NH = (size_t)Mc * Dc;
    const size_t NM = (size_t)Bc * Tc * Tc;
    cvt_h<<<(int)(NH / 2048), 256>>>(hs, hs16, NH);
    cvt_h<<<(int)(NM / 2048), 256>>>(mask, m16, NM);
    dim3 tb(32, 8), tg(Dc / 32, Dc / 32, 4);
    trans_cvt4<<<tg, tb>>>(Wq, Wk, Wv, Wo, wt);

    dim3 gq(Dc / 128, Mc / 128, 3);
    gemm_qkv<<<gq, 256, GEMM_SMEM>>>(hs16, wq16, wk16, wv16, bq, bk, bv, q, k, vt);

    dim3 ga(Hc, Bc * (Tc / 128));
    flash_tc<<<ga, 256, FA_SMEM>>>(q, k, vt, m16, attn);

    dim3 gg(Dc / 128, Mc / 128);
    gemm_oproj<<<gg, 256, GEMM_SMEM>>>(attn, wo16, bo, out);
}